// round 5
// baseline (speedup 1.0000x reference)
#include <cuda_runtime.h>
#include <cuda_bf16.h>
#include <cstdint>

// Problem constants
#define NNODES 4096       // B*N = 8*512
#define KNBR   16
#define CPOOL  256
#define GDIM   128
#define INDIM  384        // CPOOL + GDIM
#define LDIM   512
#define OUTLD  1920       // 384 + 3*512
#define WSTRIDE (1024 * 512)

// ---------------- device scratch (no allocations allowed) ----------------
__device__ float g_D   [NNODES * 1024];
__device__ float g_biasL[3 * 1024];
__device__ __align__(16) __nv_bfloat16 g_X0h[NNODES * INDIM];
__device__ __align__(16) __nv_bfloat16 g_X0l[NNODES * INDIM];
__device__ __align__(16) __nv_bfloat16 g_Xh [NNODES * LDIM];
__device__ __align__(16) __nv_bfloat16 g_Xl [NNODES * LDIM];
__device__ __align__(16) __nv_bfloat16 g_Wh [3 * WSTRIDE];
__device__ __align__(16) __nv_bfloat16 g_Wl [3 * WSTRIDE];

// ======================= helpers =======================
__device__ __forceinline__ uint32_t smem_u32(const void* p) {
    uint32_t a;
    asm("{ .reg .u64 t; cvta.to.shared.u64 t, %1; cvt.u32.u64 %0, t; }"
        : "=r"(a) : "l"(p));
    return a;
}
__device__ __forceinline__ uint32_t sw64(uint32_t o) {   // SW64 swizzle for 64B rows
    return o ^ ((o >> 3) & 0x30);
}
__device__ __forceinline__ void cp16(uint32_t dst, const void* src) {
    asm volatile("cp.async.cg.shared.global [%0], [%1], 16;" :: "r"(dst), "l"(src));
}
#define CP_COMMIT() asm volatile("cp.async.commit_group;" ::: "memory")
#define CP_WAIT(n)  asm volatile("cp.async.wait_group %0;" :: "n"(n) : "memory")

#define LDSM4(r, a) \
    asm volatile("ldmatrix.sync.aligned.m8n8.x4.shared.b16 {%0,%1,%2,%3}, [%4];" \
        : "=r"((r)[0]), "=r"((r)[1]), "=r"((r)[2]), "=r"((r)[3]) : "r"(a))

#define MMA16816(d, a, b0, b1) \
    asm volatile("mma.sync.aligned.m16n8k16.row.col.f32.bf16.bf16.f32 " \
        "{%0,%1,%2,%3}, {%4,%5,%6,%7}, {%8,%9}, {%0,%1,%2,%3};" \
        : "+f"((d)[0]), "+f"((d)[1]), "+f"((d)[2]), "+f"((d)[3]) \
        : "r"((a)[0]), "r"((a)[1]), "r"((a)[2]), "r"((a)[3]), "r"(b0), "r"(b1))

__device__ __forceinline__ void split_bf16(float v, __nv_bfloat16& h, __nv_bfloat16& l) {
    h = __float2bfloat16(v);
    l = __float2bfloat16(v - __bfloat162float(h));
}

// ======================= mma.sync GEMM =======================
// D(4096 x 1024) = X(4096 x Kin) @ W(1024 x Kin)^T + bias
// bf16 hi/lo split, 3-pass compensation, fp32 accumulation.
// CTA tile 128x128, BK=32, 8 warps (warp tile 32x64), 3-stage cp.async.
#define ARR_BYTES (128 * 64)                // 8192
#define STG_BYTES (4 * ARR_BYTES)           // 32768
#define NSTG 3
#define GEMM_SMEM (NSTG * STG_BYTES)        // 98304

__global__ __launch_bounds__(256) void gemm_mma(
    const __nv_bfloat16* __restrict__ Ah, const __nv_bfloat16* __restrict__ Al,
    const __nv_bfloat16* __restrict__ Bh, const __nv_bfloat16* __restrict__ Bl,
    const float* __restrict__ bias,
    float* __restrict__ C,      // ldc = 1024
    int Kin)
{
    extern __shared__ char smem[];
    const uint32_t sb  = smem_u32(smem);
    const int tid  = threadIdx.x;
    const int lane = tid & 31;
    const int wid  = tid >> 5;
    const int bm   = blockIdx.y * 128;
    const int bn   = blockIdx.x * 128;
    const int m0   = (wid & 3) * 32;     // warp m-offset in tile
    const int n0   = (wid >> 2) * 64;    // warp n-offset in tile

    // cp.async chunk mapping: 512 chunks of 16B per array, 2 per thread
    const int r0c = tid >> 2;            // chunk tid:      row 0..63
    const int s0c = tid & 3;             //                 seg 0..3
    const int r1c = (tid + 256) >> 2;    // chunk tid+256:  row 64..127

    const __nv_bfloat16* gsrc[4] = { Ah, Al, Bh, Bl };
    const int grow0[4] = { bm, bm, bn, bn };

    uint32_t soff0[4], soff1[4];
    #pragma unroll
    for (int a = 0; a < 4; a++) {
        soff0[a] = a * ARR_BYTES + sw64((uint32_t)(r0c * 64 + s0c * 16));
        soff1[a] = a * ARR_BYTES + sw64((uint32_t)(r1c * 64 + s0c * 16));
    }

    const int nk = Kin / 32;

    // ---- issue stages 0, 1 ----
    #pragma unroll
    for (int p = 0; p < 2; p++) {
        const uint32_t bufb = sb + (uint32_t)p * STG_BYTES;
        const int kb = p * 32;
        #pragma unroll
        for (int a = 0; a < 4; a++) {
            cp16(bufb + soff0[a], gsrc[a] + (size_t)(grow0[a] + r0c) * Kin + kb + s0c * 8);
            cp16(bufb + soff1[a], gsrc[a] + (size_t)(grow0[a] + r1c) * Kin + kb + s0c * 8);
        }
        CP_COMMIT();
    }

    float acc[2][8][4];
    #pragma unroll
    for (int i = 0; i < 2; i++)
        #pragma unroll
        for (int j = 0; j < 8; j++)
            #pragma unroll
            for (int q = 0; q < 4; q++)
                acc[i][j][q] = 0.0f;

    const int a_row = lane & 15;
    const int a_kh  = (lane >> 4) & 1;
    const int b_row = ((lane >> 4) << 3) + (lane & 7);
    const int b_kh  = (lane >> 3) & 1;

    int buf = 0;
    for (int s = 0; s < nk; s++) {
        CP_WAIT(1);
        __syncthreads();

        const uint32_t bufb = sb + (uint32_t)buf * STG_BYTES;

        #pragma unroll
        for (int kk = 0; kk < 2; kk++) {
            uint32_t fah[2][4], fal[2][4];
            #pragma unroll
            for (int mt = 0; mt < 2; mt++) {
                const uint32_t off =
                    sw64((uint32_t)((m0 + mt * 16 + a_row) * 64 + kk * 32 + a_kh * 16));
                LDSM4(fah[mt], bufb + 0 * ARR_BYTES + off);
                LDSM4(fal[mt], bufb + 1 * ARR_BYTES + off);
            }
            uint32_t fbh[4][4], fbl[4][4];
            #pragma unroll
            for (int nt = 0; nt < 4; nt++) {
                const uint32_t off =
                    sw64((uint32_t)((n0 + nt * 16 + b_row) * 64 + kk * 32 + b_kh * 16));
                LDSM4(fbh[nt], bufb + 2 * ARR_BYTES + off);
                LDSM4(fbl[nt], bufb + 3 * ARR_BYTES + off);
            }
            #pragma unroll
            for (int mt = 0; mt < 2; mt++) {
                #pragma unroll
                for (int ni = 0; ni < 8; ni++) {
                    const uint32_t bh0 = fbh[ni >> 1][(ni & 1) * 2];
                    const uint32_t bh1 = fbh[ni >> 1][(ni & 1) * 2 + 1];
                    const uint32_t bl0 = fbl[ni >> 1][(ni & 1) * 2];
                    const uint32_t bl1 = fbl[ni >> 1][(ni & 1) * 2 + 1];
                    MMA16816(acc[mt][ni], fah[mt], bh0, bh1);
                    MMA16816(acc[mt][ni], fah[mt], bl0, bl1);
                    MMA16816(acc[mt][ni], fal[mt], bh0, bh1);
                }
            }
        }

        // prefetch stage s+2 into the buffer freed at the sync above
        if (s + 2 < nk) {
            const uint32_t nb = sb + (uint32_t)((s + 2) % NSTG) * STG_BYTES;
            const int kb = (s + 2) * 32;
            #pragma unroll
            for (int a = 0; a < 4; a++) {
                cp16(nb + soff0[a], gsrc[a] + (size_t)(grow0[a] + r0c) * Kin + kb + s0c * 8);
                cp16(nb + soff1[a], gsrc[a] + (size_t)(grow0[a] + r1c) * Kin + kb + s0c * 8);
            }
        }
        CP_COMMIT();   // always commit (possibly empty) to keep group counts aligned

        buf = (buf + 1) % NSTG;
    }

    // ---- epilogue: write D with bias ----
    #pragma unroll
    for (int mt = 0; mt < 2; mt++) {
        const int r = bm + m0 + mt * 16 + (lane >> 2);
        #pragma unroll
        for (int ni = 0; ni < 8; ni++) {
            const int col = bn + n0 + ni * 8 + (lane & 3) * 2;
            const float b0 = bias[col], b1 = bias[col + 1];
            float2 v0 = { acc[mt][ni][0] + b0, acc[mt][ni][1] + b1 };
            float2 v1 = { acc[mt][ni][2] + b0, acc[mt][ni][3] + b1 };
            *(float2*)(C + (size_t)r * 1024 + col)       = v0;
            *(float2*)(C + (size_t)(r + 8) * 1024 + col) = v1;
        }
    }
}

// ======================= fused prologue =======================
// Per node: geo MLP (7->128 relu, 128->128 relu), copy pooled, write
// out[:, 0:384], and produce bf16 hi/lo of X0. One block per node.
__global__ __launch_bounds__(128) void fused_pre(
    const float* __restrict__ rois,
    const float* __restrict__ pooled,
    const float* __restrict__ gW1, const float* __restrict__ gb1,
    const float* __restrict__ gW2, const float* __restrict__ gb2,
    float* __restrict__ out,
    __nv_bfloat16* __restrict__ X0h, __nv_bfloat16* __restrict__ X0l)
{
    __shared__ float s_roi[8];
    __shared__ float s_h[GDIM];

    const int n   = blockIdx.x;
    const int tid = threadIdx.x;

    if (tid < 7) s_roi[tid] = rois[n * 7 + tid];
    __syncthreads();

    // layer 1: hidden = relu(gW1 @ roi + gb1)
    float a1 = gb1[tid];
    #pragma unroll
    for (int j = 0; j < 7; j++) a1 = fmaf(gW1[tid * 7 + j], s_roi[j], a1);
    s_h[tid] = fmaxf(a1, 0.0f);
    __syncthreads();

    // layer 2: g = relu(gW2 @ hidden + gb2)
    float a2 = gb2[tid];
    const float4* w2 = (const float4*)(gW2 + tid * GDIM);
    #pragma unroll
    for (int j = 0; j < GDIM / 4; j++) {
        float4 w = w2[j];
        a2 = fmaf(w.x, s_h[4 * j + 0], a2);
        a2 = fmaf(w.y, s_h[4 * j + 1], a2);
        a2 = fmaf(w.z, s_h[4 * j + 2], a2);
        a2 = fmaf(w.w, s_h[4 * j + 3], a2);
    }
    float g = fmaxf(a2, 0.0f);

    out[(size_t)n * OUTLD + CPOOL + tid] = g;
    __nv_bfloat16 gh, gl;
    split_bf16(g, gh, gl);
    X0h[(size_t)n * INDIM + CPOOL + tid] = gh;
    X0l[(size_t)n * INDIM + CPOOL + tid] = gl;

    // pooled: 2 columns per thread
    #pragma unroll
    for (int c = tid; c < CPOOL; c += 128) {
        float v = pooled[(size_t)n * CPOOL + c];
        out[(size_t)n * OUTLD + c] = v;
        __nv_bfloat16 h, l;
        split_bf16(v, h, l);
        X0h[(size_t)n * INDIM + c] = h;
        X0l[(size_t)n * INDIM + c] = l;
    }
}

// ======================= weight prep (all 3 layers) =======================
// Wcat = [W_l ; W_r - W_l] as bf16 hi/lo; biasL = [0 ; b]. Layer = blockIdx.y.
__global__ void prep_w3(
    const float* __restrict__ W0, const float* __restrict__ b0,
    const float* __restrict__ W1, const float* __restrict__ b1,
    const float* __restrict__ W2, const float* __restrict__ b2,
    __nv_bfloat16* __restrict__ Wh, __nv_bfloat16* __restrict__ Wl,
    float* __restrict__ biasL)
{
    const int layer = blockIdx.y;
    const float* W = (layer == 0) ? W0 : (layer == 1) ? W1 : W2;
    const float* b = (layer == 0) ? b0 : (layer == 1) ? b1 : b2;
    const int Kin  = (layer == 0) ? INDIM : LDIM;

    __nv_bfloat16* wh = Wh + (size_t)layer * WSTRIDE;
    __nv_bfloat16* wl = Wl + (size_t)layer * WSTRIDE;

    int idx = blockIdx.x * blockDim.x + threadIdx.x;
    if (idx < 512 * Kin) {
        int r = idx / Kin, c = idx % Kin;
        float vl = W[(size_t)r * 2 * Kin + c];
        float vr = W[(size_t)r * 2 * Kin + Kin + c];
        float d  = vr - vl;

        __nv_bfloat16 h, l;
        split_bf16(vl, h, l);
        wh[(size_t)r * Kin + c] = h;
        wl[(size_t)r * Kin + c] = l;
        split_bf16(d, h, l);
        wh[(size_t)(512 + r) * Kin + c] = h;
        wl[(size_t)(512 + r) * Kin + c] = l;
    }
    if (idx < 512) {
        biasL[layer * 1024 + idx]       = 0.0f;
        biasL[layer * 1024 + 512 + idx] = b[idx];
    }
}

// ---------------- aggregation + bf16 split of the new features ------------
__global__ __launch_bounds__(128) void aggregate(
    const float* __restrict__ D,
    const int*   __restrict__ src,
    __nv_bfloat16* __restrict__ Xh,  // 4096 x 512
    __nv_bfloat16* __restrict__ Xl,
    float* __restrict__ out,         // 4096 x 1920
    int out_off)
{
    const int n  = blockIdx.x;
    const int f4 = threadIdx.x;   // 0..127

    float4 c = *reinterpret_cast<const float4*>(D + (size_t)n * 1024 + 512 + f4 * 4);
    float4 m = make_float4(0.f, 0.f, 0.f, 0.f);

    #pragma unroll
    for (int k = 0; k < KNBR; k++) {
        int j = src[n * KNBR + k];
        float4 a = *reinterpret_cast<const float4*>(D + (size_t)j * 1024 + f4 * 4);
        m.x = fmaxf(m.x, a.x + c.x);
        m.y = fmaxf(m.y, a.y + c.y);
        m.z = fmaxf(m.z, a.z + c.z);
        m.w = fmaxf(m.w, a.w + c.w);
    }
    *reinterpret_cast<float4*>(out + (size_t)n * OUTLD + out_off + f4 * 4) = m;

    __nv_bfloat16 hx, hy, hz, hw, lx, ly, lz, lw;
    split_bf16(m.x, hx, lx); split_bf16(m.y, hy, ly);
    split_bf16(m.z, hz, lz); split_bf16(m.w, hw, lw);
    __nv_bfloat162 h01, h23, l01, l23;
    h01.x = hx; h01.y = hy; h23.x = hz; h23.y = hw;
    l01.x = lx; l01.y = ly; l23.x = lz; l23.y = lw;

    *reinterpret_cast<__nv_bfloat162*>(Xh + (size_t)n * LDIM + f4 * 4)     = h01;
    *reinterpret_cast<__nv_bfloat162*>(Xh + (size_t)n * LDIM + f4 * 4 + 2) = h23;
    *reinterpret_cast<__nv_bfloat162*>(Xl + (size_t)n * LDIM + f4 * 4)     = l01;
    *reinterpret_cast<__nv_bfloat162*>(Xl + (size_t)n * LDIM + f4 * 4 + 2) = l23;
}

// ---------------------------------------------------------------------------
extern "C" void kernel_launch(void* const* d_in, const int* in_sizes, int n_in,
                              void* d_out, int out_size)
{
    const float* rois   = (const float*)d_in[0];
    const float* pooled = (const float*)d_in[1];
    const int*   edge   = (const int*)  d_in[2];   // (2, 65536): row 0 = src
    const float* gW1    = (const float*)d_in[3];
    const float* gb1    = (const float*)d_in[4];
    const float* gW2    = (const float*)d_in[5];
    const float* gb2    = (const float*)d_in[6];
    const float* fcW[3] = {(const float*)d_in[7], (const float*)d_in[9],  (const float*)d_in[11]};
    const float* fcb[3] = {(const float*)d_in[8], (const float*)d_in[10], (const float*)d_in[12]};
    float* out = (float*)d_out;

    const int* src = edge;

    float *D, *biasL;
    __nv_bfloat16 *X0h, *X0l, *Xh, *Xl, *Wh, *Wl;
    cudaGetSymbolAddress((void**)&D,     g_D);
    cudaGetSymbolAddress((void**)&biasL, g_biasL);
    cudaGetSymbolAddress((void**)&X0h,   g_X0h);
    cudaGetSymbolAddress((void**)&X0l,   g_X0l);
    cudaGetSymbolAddress((void**)&Xh,    g_Xh);
    cudaGetSymbolAddress((void**)&Xl,    g_Xl);
    cudaGetSymbolAddress((void**)&Wh,    g_Wh);
    cudaGetSymbolAddress((void**)&Wl,    g_Wl);

    cudaFuncSetAttribute(gemm_mma, cudaFuncAttributeMaxDynamicSharedMemorySize, GEMM_SMEM);

    // 1) all weight prep (independent of activations)
    prep_w3<<<dim3(1024, 3), 256>>>(
        fcW[0], fcb[0], fcW[1], fcb[1], fcW[2], fcb[2], Wh, Wl, biasL);

    // 2) fused prologue: geo MLP + pooled + out[:, :384] + bf16 split
    fused_pre<<<NNODES, 128>>>(rois, pooled, gW1, gb1, gW2, gb2, out, X0h, X0l);

    // 3) three EdgeConv layers
    const int Kin[3]    = {INDIM, LDIM, LDIM};
    const int outOff[3] = {384, 384 + 512, 384 + 1024};

    for (int l = 0; l < 3; l++) {
        const __nv_bfloat16* Ah = (l == 0) ? X0h : Xh;
        const __nv_bfloat16* Al = (l == 0) ? X0l : Xl;
        gemm_mma<<<dim3(1024 / 128, NNODES / 128), 256, GEMM_SMEM>>>(
            Ah, Al, Wh + (size_t)l * WSTRIDE, Wl + (size_t)l * WSTRIDE,
            biasL + l * 1024, D, Kin[l]);

        aggregate<<<NNODES, 128>>>(D, src, Xh, Xl, out, outOff[l]);
    }
}

// round 6
// speedup vs baseline: 1.7506x; 1.7506x over previous
#include <cuda_runtime.h>
#include <cuda_bf16.h>
#include <cstdint>

// Problem constants
#define NNODES 4096       // B*N = 8*512
#define KNBR   16
#define CPOOL  256
#define GDIM   128
#define INDIM  384        // CPOOL + GDIM
#define LDIM   512
#define OUTLD  1920       // 384 + 3*512
#define WSTRIDE (1024 * 512)

// ---------------- device scratch (no allocations allowed) ----------------
__device__ float g_D   [NNODES * 1024];
__device__ float g_biasL[3 * 1024];
__device__ __align__(16) __nv_bfloat16 g_X0h[NNODES * INDIM];
__device__ __align__(16) __nv_bfloat16 g_X0l[NNODES * INDIM];
__device__ __align__(16) __nv_bfloat16 g_Xh [NNODES * LDIM];
__device__ __align__(16) __nv_bfloat16 g_Xl [NNODES * LDIM];
__device__ __align__(16) __nv_bfloat16 g_Wh [3 * WSTRIDE];
__device__ __align__(16) __nv_bfloat16 g_Wl [3 * WSTRIDE];

// ======================= helpers =======================
__device__ __forceinline__ uint32_t smem_u32(const void* p) {
    uint32_t a;
    asm("{ .reg .u64 t; cvta.to.shared.u64 t, %1; cvt.u32.u64 %0, t; }"
        : "=r"(a) : "l"(p));
    return a;
}
__device__ __forceinline__ uint32_t sw64(uint32_t o) {   // SW64 swizzle for 64B rows
    return o ^ ((o >> 3) & 0x30);
}
__device__ __forceinline__ void cp16(uint32_t dst, const void* src) {
    asm volatile("cp.async.cg.shared.global [%0], [%1], 16;" :: "r"(dst), "l"(src));
}
#define CP_COMMIT() asm volatile("cp.async.commit_group;" ::: "memory")
#define CP_WAIT(n)  asm volatile("cp.async.wait_group %0;" :: "n"(n) : "memory")

#define LDSM4(r, a) \
    asm volatile("ldmatrix.sync.aligned.m8n8.x4.shared.b16 {%0,%1,%2,%3}, [%4];" \
        : "=r"((r)[0]), "=r"((r)[1]), "=r"((r)[2]), "=r"((r)[3]) : "r"(a))

#define MMA16816(d, a, b0, b1) \
    asm volatile("mma.sync.aligned.m16n8k16.row.col.f32.bf16.bf16.f32 " \
        "{%0,%1,%2,%3}, {%4,%5,%6,%7}, {%8,%9}, {%0,%1,%2,%3};" \
        : "+f"((d)[0]), "+f"((d)[1]), "+f"((d)[2]), "+f"((d)[3]) \
        : "r"((a)[0]), "r"((a)[1]), "r"((a)[2]), "r"((a)[3]), "r"(b0), "r"(b1))

__device__ __forceinline__ void split_bf16(float v, __nv_bfloat16& h, __nv_bfloat16& l) {
    h = __float2bfloat16(v);
    l = __float2bfloat16(v - __bfloat162float(h));
}

// ======================= mma.sync GEMM (round-4 known-good) ================
// D(4096 x 1024) = X(4096 x Kin) @ W(1024 x Kin)^T + bias
// bf16 hi/lo split, 3-pass compensation, fp32 accumulation.
// CTA tile 128x128, BK=32, 8 warps (warp tile 32x64), cp.async double buffer.
#define ARR_BYTES (128 * 64)                // 8192
#define STG_BYTES (4 * ARR_BYTES)           // 32768
#define GEMM_SMEM (2 * STG_BYTES)           // 65536

__global__ __launch_bounds__(256) void gemm_mma(
    const __nv_bfloat16* __restrict__ Ah, const __nv_bfloat16* __restrict__ Al,
    const __nv_bfloat16* __restrict__ Bh, const __nv_bfloat16* __restrict__ Bl,
    const float* __restrict__ bias,
    float* __restrict__ C,      // ldc = 1024
    int Kin)
{
    extern __shared__ char smem[];
    const uint32_t sb  = smem_u32(smem);
    const int tid  = threadIdx.x;
    const int lane = tid & 31;
    const int wid  = tid >> 5;
    const int bm   = blockIdx.y * 128;
    const int bn   = blockIdx.x * 128;
    const int m0   = (wid & 3) * 32;     // warp m-offset in tile
    const int n0   = (wid >> 2) * 64;    // warp n-offset in tile

    // cp.async chunk mapping: 512 chunks of 16B per array, 2 per thread
    const int r0c = tid >> 2;            // chunk tid:      row 0..63
    const int s0c = tid & 3;             //                 seg 0..3
    const int r1c = (tid + 256) >> 2;    // chunk tid+256:  row 64..127
    const int s1c = s0c;

    const __nv_bfloat16* gsrc[4] = { Ah, Al, Bh, Bl };
    const int grow0[4] = { bm, bm, bn, bn };

    // per-thread smem store offsets (swizzled, stage-relative)
    uint32_t soff0[4], soff1[4];
    #pragma unroll
    for (int a = 0; a < 4; a++) {
        soff0[a] = a * ARR_BYTES + sw64((uint32_t)(r0c * 64 + s0c * 16));
        soff1[a] = a * ARR_BYTES + sw64((uint32_t)(r1c * 64 + s1c * 16));
    }

    const int nk = Kin / 32;

    // ---- issue stage 0 ----
    {
        const uint32_t bufb = sb;
        #pragma unroll
        for (int a = 0; a < 4; a++) {
            cp16(bufb + soff0[a], gsrc[a] + (size_t)(grow0[a] + r0c) * Kin + s0c * 8);
            cp16(bufb + soff1[a], gsrc[a] + (size_t)(grow0[a] + r1c) * Kin + s1c * 8);
        }
        CP_COMMIT();
    }

    float acc[2][8][4];
    #pragma unroll
    for (int i = 0; i < 2; i++)
        #pragma unroll
        for (int j = 0; j < 8; j++)
            #pragma unroll
            for (int q = 0; q < 4; q++)
                acc[i][j][q] = 0.0f;

    // ldmatrix per-lane address components
    const int a_row = lane & 15;             // row within m16 tile
    const int a_kh  = (lane >> 4) & 1;       // k half (0/8)
    const int b_row = ((lane >> 4) << 3) + (lane & 7);  // row within n16 pair
    const int b_kh  = (lane >> 3) & 1;

    for (int s = 0; s < nk; s++) {
        const uint32_t bufb = sb + (uint32_t)(s & 1) * STG_BYTES;

        if (s + 1 < nk) {
            const uint32_t nb = sb + (uint32_t)((s + 1) & 1) * STG_BYTES;
            const int kb = (s + 1) * 32;
            #pragma unroll
            for (int a = 0; a < 4; a++) {
                cp16(nb + soff0[a], gsrc[a] + (size_t)(grow0[a] + r0c) * Kin + kb + s0c * 8);
                cp16(nb + soff1[a], gsrc[a] + (size_t)(grow0[a] + r1c) * Kin + kb + s1c * 8);
            }
            CP_COMMIT();
            CP_WAIT(1);
        } else {
            CP_WAIT(0);
        }
        __syncthreads();

        #pragma unroll
        for (int kk = 0; kk < 2; kk++) {
            uint32_t fah[2][4], fal[2][4];
            #pragma unroll
            for (int mt = 0; mt < 2; mt++) {
                const uint32_t off =
                    sw64((uint32_t)((m0 + mt * 16 + a_row) * 64 + kk * 32 + a_kh * 16));
                LDSM4(fah[mt], bufb + 0 * ARR_BYTES + off);
                LDSM4(fal[mt], bufb + 1 * ARR_BYTES + off);
            }
            uint32_t fbh[4][4], fbl[4][4];
            #pragma unroll
            for (int nt = 0; nt < 4; nt++) {
                const uint32_t off =
                    sw64((uint32_t)((n0 + nt * 16 + b_row) * 64 + kk * 32 + b_kh * 16));
                LDSM4(fbh[nt], bufb + 2 * ARR_BYTES + off);
                LDSM4(fbl[nt], bufb + 3 * ARR_BYTES + off);
            }
            #pragma unroll
            for (int mt = 0; mt < 2; mt++) {
                #pragma unroll
                for (int ni = 0; ni < 8; ni++) {
                    const uint32_t bh0 = fbh[ni >> 1][(ni & 1) * 2];
                    const uint32_t bh1 = fbh[ni >> 1][(ni & 1) * 2 + 1];
                    const uint32_t bl0 = fbl[ni >> 1][(ni & 1) * 2];
                    const uint32_t bl1 = fbl[ni >> 1][(ni & 1) * 2 + 1];
                    MMA16816(acc[mt][ni], fah[mt], bh0, bh1);
                    MMA16816(acc[mt][ni], fah[mt], bl0, bl1);
                    MMA16816(acc[mt][ni], fal[mt], bh0, bh1);
                }
            }
        }
        __syncthreads();
    }

    // ---- epilogue: write D with bias ----
    #pragma unroll
    for (int mt = 0; mt < 2; mt++) {
        const int r = bm + m0 + mt * 16 + (lane >> 2);
        #pragma unroll
        for (int ni = 0; ni < 8; ni++) {
            const int col = bn + n0 + ni * 8 + (lane & 3) * 2;
            const float b0 = bias[col], b1 = bias[col + 1];
            float2 v0 = { acc[mt][ni][0] + b0, acc[mt][ni][1] + b1 };
            float2 v1 = { acc[mt][ni][2] + b0, acc[mt][ni][3] + b1 };
            *(float2*)(C + (size_t)r * 1024 + col)       = v0;
            *(float2*)(C + (size_t)(r + 8) * 1024 + col) = v1;
        }
    }
}

// ======================= fused prologue =======================
// Per node: geo MLP (7->128 relu, 128->128 relu), copy pooled, write
// out[:, 0:384], and produce bf16 hi/lo of X0. One block per node.
__global__ __launch_bounds__(128) void fused_pre(
    const float* __restrict__ rois,
    const float* __restrict__ pooled,
    const float* __restrict__ gW1, const float* __restrict__ gb1,
    const float* __restrict__ gW2, const float* __restrict__ gb2,
    float* __restrict__ out,
    __nv_bfloat16* __restrict__ X0h, __nv_bfloat16* __restrict__ X0l)
{
    __shared__ float s_roi[8];
    __shared__ float s_h[GDIM];

    const int n   = blockIdx.x;
    const int tid = threadIdx.x;

    if (tid < 7) s_roi[tid] = rois[n * 7 + tid];
    __syncthreads();

    // layer 1: hidden = relu(gW1 @ roi + gb1)
    float a1 = gb1[tid];
    #pragma unroll
    for (int j = 0; j < 7; j++) a1 = fmaf(gW1[tid * 7 + j], s_roi[j], a1);
    s_h[tid] = fmaxf(a1, 0.0f);
    __syncthreads();

    // layer 2: g = relu(gW2 @ hidden + gb2)
    float a2 = gb2[tid];
    const float4* w2 = (const float4*)(gW2 + tid * GDIM);
    #pragma unroll
    for (int j = 0; j < GDIM / 4; j++) {
        float4 w = w2[j];
        a2 = fmaf(w.x, s_h[4 * j + 0], a2);
        a2 = fmaf(w.y, s_h[4 * j + 1], a2);
        a2 = fmaf(w.z, s_h[4 * j + 2], a2);
        a2 = fmaf(w.w, s_h[4 * j + 3], a2);
    }
    float g = fmaxf(a2, 0.0f);

    out[(size_t)n * OUTLD + CPOOL + tid] = g;
    __nv_bfloat16 gh, gl;
    split_bf16(g, gh, gl);
    X0h[(size_t)n * INDIM + CPOOL + tid] = gh;
    X0l[(size_t)n * INDIM + CPOOL + tid] = gl;

    // pooled: 2 columns per thread
    #pragma unroll
    for (int c = tid; c < CPOOL; c += 128) {
        float v = pooled[(size_t)n * CPOOL + c];
        out[(size_t)n * OUTLD + c] = v;
        __nv_bfloat16 h, l;
        split_bf16(v, h, l);
        X0h[(size_t)n * INDIM + c] = h;
        X0l[(size_t)n * INDIM + c] = l;
    }
}

// ======================= weight prep (all 3 layers) =======================
// Wcat = [W_l ; W_r - W_l] as bf16 hi/lo; biasL = [0 ; b]. Layer = blockIdx.y.
__global__ void prep_w3(
    const float* __restrict__ W0, const float* __restrict__ b0,
    const float* __restrict__ W1, const float* __restrict__ b1,
    const float* __restrict__ W2, const float* __restrict__ b2,
    __nv_bfloat16* __restrict__ Wh, __nv_bfloat16* __restrict__ Wl,
    float* __restrict__ biasL)
{
    const int layer = blockIdx.y;
    const float* W = (layer == 0) ? W0 : (layer == 1) ? W1 : W2;
    const float* b = (layer == 0) ? b0 : (layer == 1) ? b1 : b2;
    const int Kin  = (layer == 0) ? INDIM : LDIM;

    __nv_bfloat16* wh = Wh + (size_t)layer * WSTRIDE;
    __nv_bfloat16* wl = Wl + (size_t)layer * WSTRIDE;

    int idx = blockIdx.x * blockDim.x + threadIdx.x;
    if (idx < 512 * Kin) {
        int r = idx / Kin, c = idx % Kin;
        float vl = W[(size_t)r * 2 * Kin + c];
        float vr = W[(size_t)r * 2 * Kin + Kin + c];
        float d  = vr - vl;

        __nv_bfloat16 h, l;
        split_bf16(vl, h, l);
        wh[(size_t)r * Kin + c] = h;
        wl[(size_t)r * Kin + c] = l;
        split_bf16(d, h, l);
        wh[(size_t)(512 + r) * Kin + c] = h;
        wl[(size_t)(512 + r) * Kin + c] = l;
    }
    if (idx < 512) {
        biasL[layer * 1024 + idx]       = 0.0f;
        biasL[layer * 1024 + 512 + idx] = b[idx];
    }
}

// ---------------- aggregation + bf16 split of the new features ------------
__global__ __launch_bounds__(128) void aggregate(
    const float* __restrict__ D,
    const int*   __restrict__ src,
    __nv_bfloat16* __restrict__ Xh,  // 4096 x 512
    __nv_bfloat16* __restrict__ Xl,
    float* __restrict__ out,         // 4096 x 1920
    int out_off)
{
    const int n  = blockIdx.x;
    const int f4 = threadIdx.x;   // 0..127

    float4 c = *reinterpret_cast<const float4*>(D + (size_t)n * 1024 + 512 + f4 * 4);
    float4 m = make_float4(0.f, 0.f, 0.f, 0.f);

    #pragma unroll
    for (int k = 0; k < KNBR; k++) {
        int j = src[n * KNBR + k];
        float4 a = *reinterpret_cast<const float4*>(D + (size_t)j * 1024 + f4 * 4);
        m.x = fmaxf(m.x, a.x + c.x);
        m.y = fmaxf(m.y, a.y + c.y);
        m.z = fmaxf(m.z, a.z + c.z);
        m.w = fmaxf(m.w, a.w + c.w);
    }
    *reinterpret_cast<float4*>(out + (size_t)n * OUTLD + out_off + f4 * 4) = m;

    __nv_bfloat16 hx, hy, hz, hw, lx, ly, lz, lw;
    split_bf16(m.x, hx, lx); split_bf16(m.y, hy, ly);
    split_bf16(m.z, hz, lz); split_bf16(m.w, hw, lw);
    __nv_bfloat162 h01, h23, l01, l23;
    h01.x = hx; h01.y = hy; h23.x = hz; h23.y = hw;
    l01.x = lx; l01.y = ly; l23.x = lz; l23.y = lw;

    *reinterpret_cast<__nv_bfloat162*>(Xh + (size_t)n * LDIM + f4 * 4)     = h01;
    *reinterpret_cast<__nv_bfloat162*>(Xh + (size_t)n * LDIM + f4 * 4 + 2) = h23;
    *reinterpret_cast<__nv_bfloat162*>(Xl + (size_t)n * LDIM + f4 * 4)     = l01;
    *reinterpret_cast<__nv_bfloat162*>(Xl + (size_t)n * LDIM + f4 * 4 + 2) = l23;
}

// ---------------------------------------------------------------------------
extern "C" void kernel_launch(void* const* d_in, const int* in_sizes, int n_in,
                              void* d_out, int out_size)
{
    const float* rois   = (const float*)d_in[0];
    const float* pooled = (const float*)d_in[1];
    const int*   edge   = (const int*)  d_in[2];   // (2, 65536): row 0 = src
    const float* gW1    = (const float*)d_in[3];
    const float* gb1    = (const float*)d_in[4];
    const float* gW2    = (const float*)d_in[5];
    const float* gb2    = (const float*)d_in[6];
    const float* fcW[3] = {(const float*)d_in[7], (const float*)d_in[9],  (const float*)d_in[11]};
    const float* fcb[3] = {(const float*)d_in[8], (const float*)d_in[10], (const float*)d_in[12]};
    float* out = (float*)d_out;

    const int* src = edge;

    float *D, *biasL;
    __nv_bfloat16 *X0h, *X0l, *Xh, *Xl, *Wh, *Wl;
    cudaGetSymbolAddress((void**)&D,     g_D);
    cudaGetSymbolAddress((void**)&biasL, g_biasL);
    cudaGetSymbolAddress((void**)&X0h,   g_X0h);
    cudaGetSymbolAddress((void**)&X0l,   g_X0l);
    cudaGetSymbolAddress((void**)&Xh,    g_Xh);
    cudaGetSymbolAddress((void**)&Xl,    g_Xl);
    cudaGetSymbolAddress((void**)&Wh,    g_Wh);
    cudaGetSymbolAddress((void**)&Wl,    g_Wl);

    cudaFuncSetAttribute(gemm_mma, cudaFuncAttributeMaxDynamicSharedMemorySize, GEMM_SMEM);

    // 1) all weight prep (independent of activations)
    prep_w3<<<dim3(1024, 3), 256>>>(
        fcW[0], fcb[0], fcW[1], fcb[1], fcW[2], fcb[2], Wh, Wl, biasL);

    // 2) fused prologue: geo MLP + pooled + out[:, :384] + bf16 split
    fused_pre<<<NNODES, 128>>>(rois, pooled, gW1, gb1, gW2, gb2, out, X0h, X0l);

    // 3) three EdgeConv layers
    const int Kin[3]    = {INDIM, LDIM, LDIM};
    const int outOff[3] = {384, 384 + 512, 384 + 1024};

    for (int l = 0; l < 3; l++) {
        const __nv_bfloat16* Ah = (l == 0) ? X0h : Xh;
        const __nv_bfloat16* Al = (l == 0) ? X0l : Xl;
        gemm_mma<<<dim3(1024 / 128, NNODES / 128), 256, GEMM_SMEM>>>(
            Ah, Al, Wh + (size_t)l * WSTRIDE, Wl + (size_t)l * WSTRIDE,
            biasL + l * 1024, D, Kin[l]);

        aggregate<<<NNODES, 128>>>(D, src, Xh, Xl, out, outOff[l]);
    }
}